// round 2
// baseline (speedup 1.0000x reference)
#include <cuda_runtime.h>
#include <math.h>

#define LL 512
#define CS 384
#define CZ 256
#define PW 1152
#define SH 3648
#define WLL 0.57735026918962576f
#define WCC 0.23570226039551584f

__device__ float g_Wcat[CS * PW];
__device__ float g_proj[LL * PW];   // [q 0|k 192|v 384|qp 576|kp 720|vp 864]
__device__ float g_R[LL * 9];
__device__ float g_t[LL * 3];
__device__ float g_coef[12];
__device__ float g_qpp[LL * 144];
__device__ float g_kpp[LL * 144];
__device__ float g_vpp[LL * 288];
__device__ float g_shid[LL * SH];
__device__ float g_parts[4 * LL * CS];
__device__ float g_pre[LL * CS];
__device__ float g_s1[LL * CS];
__device__ float g_h1[LL * CS];
__device__ float g_h2[LL * CS];

__global__ void pack_w(const float* __restrict__ Wq, const float* __restrict__ Wk,
                       const float* __restrict__ Wv, const float* __restrict__ Wqp,
                       const float* __restrict__ Wkp, const float* __restrict__ Wvp)
{
    int idx = blockIdx.x * blockDim.x + threadIdx.x;
    if (idx >= CS * PW) return;
    int r = idx / PW, c = idx - r * PW;
    float v;
    if      (c < 192)  v = Wq [r*192 + c];
    else if (c < 384)  v = Wk [r*192 + c-192];
    else if (c < 576)  v = Wv [r*192 + c-384];
    else if (c < 720)  v = Wqp[r*144 + c-576];
    else if (c < 864)  v = Wkp[r*144 + c-720];
    else               v = Wvp[r*288 + c-864];
    g_Wcat[idx] = v;
}

__global__ void prep(const float* __restrict__ quat, const float* __restrict__ trsl,
                     const float* __restrict__ scale)
{
    int i = blockIdx.x * blockDim.x + threadIdx.x;
    if (i < LL) {
        float w = quat[i*4], x = quat[i*4+1], y = quat[i*4+2], z = quat[i*4+3];
        float inv = rsqrtf(w*w + x*x + y*y + z*z);
        w *= inv; x *= inv; y *= inv; z *= inv;
        float* R = g_R + i*9;
        R[0]=1.f-2.f*(y*y+z*z); R[1]=2.f*(x*y-w*z);     R[2]=2.f*(x*z+w*y);
        R[3]=2.f*(x*y+w*z);     R[4]=1.f-2.f*(x*x+z*z); R[5]=2.f*(y*z-w*x);
        R[6]=2.f*(x*z-w*y);     R[7]=2.f*(y*z+w*x);     R[8]=1.f-2.f*(x*x+y*y);
        g_t[i*3]=trsl[i*3]; g_t[i*3+1]=trsl[i*3+1]; g_t[i*3+2]=trsl[i*3+2];
    }
    if (i < 12) g_coef[i] = 0.5f * WCC * log1pf(expf(scale[i]));
}

__global__ void transform()
{
    int i = blockIdx.x, pt = threadIdx.x;   // 192 points
    const float* R = g_R + i*9;
    const float* t = g_t + i*3;
    const float* src; float* dst;
    if (pt < 48)      { src = g_proj + (size_t)i*PW + 576 + pt*3;      dst = g_qpp + i*144 + pt*3; }
    else if (pt < 96) { src = g_proj + (size_t)i*PW + 720 + (pt-48)*3; dst = g_kpp + i*144 + (pt-48)*3; }
    else              { src = g_proj + (size_t)i*PW + 864 + (pt-96)*3; dst = g_vpp + i*288 + (pt-96)*3; }
    float px = src[0], py = src[1], pz = src[2];
    dst[0] = R[0]*px + R[1]*py + R[2]*pz + t[0];
    dst[1] = R[3]*px + R[4]*py + R[5]*pz + t[1];
    dst[2] = R[6]*px + R[7]*py + R[8]*pz + t[2];
}

// 64x64 tile SGEMM, 256 threads, 4x4 per thread, optional split-K along gridDim.z
__global__ __launch_bounds__(256) void gemm64(const float* __restrict__ A,
                                              const float* __restrict__ B,
                                              float* __restrict__ C,
                                              int lda, int ldb, int ldc,
                                              int kSlice, int K, int partStride)
{
    __shared__ float As[16][64];
    __shared__ float Bs[16][64];
    int n0 = blockIdx.x * 64, m0 = blockIdx.y * 64;
    int k0 = blockIdx.z * kSlice;
    int kend = min(K, k0 + kSlice);
    float* Cc = C + (size_t)blockIdx.z * partStride;
    int tid = threadIdx.x;
    int tx = tid & 15, ty = tid >> 4;
    int ar = tid >> 2, ac = (tid & 3) << 2;
    float acc[4][4] = {};
    for (int kt = k0; kt < kend; kt += 16) {
        float4 av = *(const float4*)(A + (size_t)(m0 + ar) * lda + kt + ac);
        As[ac+0][ar] = av.x; As[ac+1][ar] = av.y; As[ac+2][ar] = av.z; As[ac+3][ar] = av.w;
        *(float4*)&Bs[ty][tx << 2] = *(const float4*)(B + (size_t)(kt + ty) * ldb + n0 + (tx << 2));
        __syncthreads();
        #pragma unroll
        for (int kk = 0; kk < 16; kk++) {
            float4 a = *(float4*)&As[kk][ty << 2];
            float4 b = *(float4*)&Bs[kk][tx << 2];
            acc[0][0]=fmaf(a.x,b.x,acc[0][0]); acc[0][1]=fmaf(a.x,b.y,acc[0][1]);
            acc[0][2]=fmaf(a.x,b.z,acc[0][2]); acc[0][3]=fmaf(a.x,b.w,acc[0][3]);
            acc[1][0]=fmaf(a.y,b.x,acc[1][0]); acc[1][1]=fmaf(a.y,b.y,acc[1][1]);
            acc[1][2]=fmaf(a.y,b.z,acc[1][2]); acc[1][3]=fmaf(a.y,b.w,acc[1][3]);
            acc[2][0]=fmaf(a.z,b.x,acc[2][0]); acc[2][1]=fmaf(a.z,b.y,acc[2][1]);
            acc[2][2]=fmaf(a.z,b.z,acc[2][2]); acc[2][3]=fmaf(a.z,b.w,acc[2][3]);
            acc[3][0]=fmaf(a.w,b.x,acc[3][0]); acc[3][1]=fmaf(a.w,b.y,acc[3][1]);
            acc[3][2]=fmaf(a.w,b.z,acc[3][2]); acc[3][3]=fmaf(a.w,b.w,acc[3][3]);
        }
        __syncthreads();
    }
    #pragma unroll
    for (int r = 0; r < 4; r++)
        *(float4*)(Cc + (size_t)(m0 + (ty<<2) + r) * ldc + n0 + (tx<<2)) =
            make_float4(acc[r][0], acc[r][1], acc[r][2], acc[r][3]);
}

__global__ void combine(const float* __restrict__ parts, int nparts, int partStride,
                        const float* __restrict__ bias, const float* __restrict__ resid,
                        float* __restrict__ out, int total, int N, int relu)
{
    int idx = blockIdx.x * blockDim.x + threadIdx.x;
    if (idx >= total) return;
    float v = parts[idx];
    for (int p = 1; p < nparts; p++) v += parts[(size_t)p * partStride + idx];
    if (bias)  v += bias[idx % N];
    if (resid) v += resid[idx];
    if (relu)  v = fmaxf(v, 0.f);
    out[idx] = v;
}

__global__ void lnorm(const float* __restrict__ in, const float* __restrict__ gg,
                      const float* __restrict__ bb, float* __restrict__ out)
{
    int i = blockIdx.x, t = threadIdx.x;   // 128 threads
    const float* x = in + (size_t)i * CS;
    float v0 = x[t], v1 = x[t+128], v2 = x[t+256];
    float s = v0+v1+v2, q = v0*v0+v1*v1+v2*v2;
    #pragma unroll
    for (int o = 16; o; o >>= 1) {
        s += __shfl_xor_sync(0xffffffffu, s, o);
        q += __shfl_xor_sync(0xffffffffu, q, o);
    }
    __shared__ float ss[4], sq[4];
    int w = t >> 5, lane = t & 31;
    if (lane == 0) { ss[w] = s; sq[w] = q; }
    __syncthreads();
    if (t == 0) {
        float S = ss[0]+ss[1]+ss[2]+ss[3], Q = sq[0]+sq[1]+sq[2]+sq[3];
        float m = S * (1.f/CS);
        ss[0] = m; sq[0] = rsqrtf(Q*(1.f/CS) - m*m + 1e-5f);
    }
    __syncthreads();
    float m = ss[0], r = sq[0];
    float* o = out + (size_t)i * CS;
    o[t]     = (v0-m)*r*gg[t]     + bb[t];
    o[t+128] = (v1-m)*r*gg[t+128] + bb[t+128];
    o[t+256] = (v2-m)*r*gg[t+256] + bb[t+256];
}

// fused attention: one CTA per query row i
__global__ __launch_bounds__(256) void attn(const float* __restrict__ z,
                                            const float* __restrict__ Wb)
{
    __shared__ float sA[LL * 12];     // 24 KB logits/weights
    __shared__ float sWb[CZ * 12];    // 12 KB
    __shared__ float sq[192], sqpp[144], sR[9], st3[3], scoef[12], sOVP[288];

    int i = blockIdx.x, tid = threadIdx.x;
    int lane = tid & 31, w = tid >> 5;
    const float* zrow = z + (size_t)i * LL * CZ;

    for (int x = tid; x < CZ*12; x += 256) sWb[x] = Wb[x];
    if (tid < 192) sq[tid] = g_proj[(size_t)i * PW + tid];
    if (tid < 144) sqpp[tid] = g_qpp[i*144 + tid];
    if (tid < 9)   sR[tid] = g_R[i*9 + tid];
    if (tid < 3)   st3[tid] = g_t[i*3 + tid];
    if (tid < 12)  scoef[tid] = g_coef[tid];
    __syncthreads();

    // ---- logits: each thread owns j = tid, tid+256 ----
    #pragma unroll
    for (int jj = 0; jj < 2; jj++) {
        int j = tid + jj * 256;
        const float* zr = zrow + (size_t)j * CZ;
        float acc[12] = {};
        for (int c = 0; c < CZ; c += 4) {
            float4 zv = *(const float4*)(zr + c);
            #pragma unroll
            for (int h = 0; h < 12; h++) {
                float a = fmaf(zv.x, sWb[(c+0)*12+h], acc[h]);
                a = fmaf(zv.y, sWb[(c+1)*12+h], a);
                a = fmaf(zv.z, sWb[(c+2)*12+h], a);
                acc[h] = fmaf(zv.w, sWb[(c+3)*12+h], a);
            }
        }
        const float* kr  = g_proj + (size_t)j * PW + 192;
        const float* kpr = g_kpp + j * 144;
        #pragma unroll
        for (int h = 0; h < 12; h++) {
            float qk = 0.f;
            #pragma unroll
            for (int d = 0; d < 16; d++) qk = fmaf(sq[h*16+d], kr[h*16+d], qk);
            float d2 = 0.f;
            #pragma unroll
            for (int e = 0; e < 12; e++) { float dd = sqpp[h*12+e] - kpr[h*12+e]; d2 = fmaf(dd, dd, d2); }
            sA[j*12 + h] = WLL * (qk * 0.25f + acc[h] - scoef[h] * d2);
        }
    }
    __syncthreads();

    // ---- softmax over j for each head ----
    for (int h = w; h < 12; h += 8) {
        float m = -1e30f;
        for (int j = lane; j < LL; j += 32) m = fmaxf(m, sA[j*12+h]);
        #pragma unroll
        for (int o = 16; o; o >>= 1) m = fmaxf(m, __shfl_xor_sync(0xffffffffu, m, o));
        float sum = 0.f;
        for (int j = lane; j < LL; j += 32) {
            float e = __expf(sA[j*12+h] - m);
            sA[j*12+h] = e; sum += e;
        }
        #pragma unroll
        for (int o = 16; o; o >>= 1) sum += __shfl_xor_sync(0xffffffffu, sum, o);
        float inv = 1.f / sum;
        for (int j = lane; j < LL; j += 32) sA[j*12+h] *= inv;
    }
    __syncthreads();

    // ---- op = a^T @ z : 4 head-triples x 64 col-quads ----
    {
        int h0 = (tid >> 6) * 3;
        int cc = (tid & 63) << 2;
        float acc[3][4] = {};
        for (int j = 0; j < LL; j++) {
            float4 zv = *(const float4*)(zrow + (size_t)j * CZ + cc);
            float a0 = sA[j*12+h0], a1 = sA[j*12+h0+1], a2 = sA[j*12+h0+2];
            acc[0][0]=fmaf(a0,zv.x,acc[0][0]); acc[0][1]=fmaf(a0,zv.y,acc[0][1]);
            acc[0][2]=fmaf(a0,zv.z,acc[0][2]); acc[0][3]=fmaf(a0,zv.w,acc[0][3]);
            acc[1][0]=fmaf(a1,zv.x,acc[1][0]); acc[1][1]=fmaf(a1,zv.y,acc[1][1]);
            acc[1][2]=fmaf(a1,zv.z,acc[1][2]); acc[1][3]=fmaf(a1,zv.w,acc[1][3]);
            acc[2][0]=fmaf(a2,zv.x,acc[2][0]); acc[2][1]=fmaf(a2,zv.y,acc[2][1]);
            acc[2][2]=fmaf(a2,zv.z,acc[2][2]); acc[2][3]=fmaf(a2,zv.w,acc[2][3]);
        }
        float* orow = g_shid + (size_t)i * SH;
        #pragma unroll
        for (int hh = 0; hh < 3; hh++)
            *(float4*)(orow + (h0+hh)*304 + cc) =
                make_float4(acc[hh][0], acc[hh][1], acc[hh][2], acc[hh][3]);
    }

    // ---- ov (16 dims) + ovp_g (24 dims) per head: 240 threads ----
    if (tid < 240) {
        int h = tid / 20, o = (tid % 20) * 2;
        const float* src; int stride;
        if (o < 16) { src = g_proj + 384 + h*16 + o;     stride = PW;  }
        else        { src = g_vpp + h*24 + (o-16);       stride = 288; }
        float a0 = 0.f, a1 = 0.f;
        for (int j = 0; j < LL; j++) {
            float av = sA[j*12 + h];
            float2 vv = *(const float2*)(src + (size_t)j * stride);
            a0 = fmaf(av, vv.x, a0);
            a1 = fmaf(av, vv.y, a1);
        }
        float* orow = g_shid + (size_t)i * SH + h * 304;
        if (o < 16) { orow[256+o] = a0; orow[257+o] = a1; }
        else        { sOVP[h*24 + o-16] = a0; sOVP[h*24 + o-15] = a1; }
    }
    __syncthreads();

    // ---- ovp = R^T (ovp_g - t), plus norms ----
    if (tid < 96) {
        int h = tid >> 3, vv = tid & 7;
        float gx = sOVP[h*24 + vv*3 + 0] - st3[0];
        float gy = sOVP[h*24 + vv*3 + 1] - st3[1];
        float gz = sOVP[h*24 + vv*3 + 2] - st3[2];
        float lx = sR[0]*gx + sR[3]*gy + sR[6]*gz;
        float ly = sR[1]*gx + sR[4]*gy + sR[7]*gz;
        float lz = sR[2]*gx + sR[5]*gy + sR[8]*gz;
        float* orow = g_shid + (size_t)i * SH + h * 304;
        orow[272 + vv*3 + 0] = lx;
        orow[272 + vv*3 + 1] = ly;
        orow[272 + vv*3 + 2] = lz;
        orow[296 + vv] = sqrtf(lx*lx + ly*ly + lz*lz);
    }
}

extern "C" void kernel_launch(void* const* d_in, const int* in_sizes, int n_in,
                              void* d_out, int out_size)
{
    const float* s    = (const float*)d_in[0];
    const float* z    = (const float*)d_in[1];
    const float* quat = (const float*)d_in[2];
    const float* trsl = (const float*)d_in[3];
    const float* Wq   = (const float*)d_in[4];
    const float* Wk   = (const float*)d_in[5];
    const float* Wv   = (const float*)d_in[6];
    const float* Wqp  = (const float*)d_in[7];
    const float* Wkp  = (const float*)d_in[8];
    const float* Wvp  = (const float*)d_in[9];
    const float* Wb   = (const float*)d_in[10];
    const float* Ws   = (const float*)d_in[11];
    const float* bs   = (const float*)d_in[12];
    const float* scale= (const float*)d_in[13];
    const float* g1   = (const float*)d_in[14];
    const float* b1   = (const float*)d_in[15];
    const float* Wm1  = (const float*)d_in[16];
    const float* bm1  = (const float*)d_in[17];
    const float* Wm2  = (const float*)d_in[18];
    const float* bm2  = (const float*)d_in[19];
    const float* Wm3  = (const float*)d_in[20];
    const float* bm3  = (const float*)d_in[21];
    const float* g2   = (const float*)d_in[22];
    const float* b2   = (const float*)d_in[23];
    float* out = (float*)d_out;

    void *pWcat, *pProj, *pShid, *pParts, *pPre, *pS1, *pH1, *pH2;
    cudaGetSymbolAddress(&pWcat,  g_Wcat);
    cudaGetSymbolAddress(&pProj,  g_proj);
    cudaGetSymbolAddress(&pShid,  g_shid);
    cudaGetSymbolAddress(&pParts, g_parts);
    cudaGetSymbolAddress(&pPre,   g_pre);
    cudaGetSymbolAddress(&pS1,    g_s1);
    cudaGetSymbolAddress(&pH1,    g_h1);
    cudaGetSymbolAddress(&pH2,    g_h2);
    float* Wcat = (float*)pWcat;  float* proj = (float*)pProj;
    float* shid = (float*)pShid;  float* parts = (float*)pParts;
    float* pre  = (float*)pPre;   float* s1 = (float*)pS1;
    float* h1   = (float*)pH1;    float* h2 = (float*)pH2;

    const int TOT = LL * CS;

    pack_w<<<(CS*PW + 255)/256, 256>>>(Wq, Wk, Wv, Wqp, Wkp, Wvp);
    prep<<<2, 256>>>(quat, trsl, scale);
    // projections: s[512,384] @ Wcat[384,1152]
    gemm64<<<dim3(PW/64, LL/64, 1), 256>>>(s, Wcat, proj, CS, PW, PW, CS, CS, 0);
    transform<<<LL, 192>>>();
    attn<<<LL, 256>>>(z, Wb);
    // shid[512,3648] @ Ws[3648,384], split-K=4
    gemm64<<<dim3(CS/64, LL/64, 4), 256>>>(shid, Ws, parts, SH, CS, CS, SH/4, SH, TOT);
    combine<<<(TOT+255)/256, 256>>>(parts, 4, TOT, bs, s, pre, TOT, CS, 0);
    lnorm<<<LL, 128>>>(pre, g1, b1, s1);
    // MLP (split-K=3 each)
    gemm64<<<dim3(CS/64, LL/64, 3), 256>>>(s1, Wm1, parts, CS, CS, CS, CS/3, CS, TOT);
    combine<<<(TOT+255)/256, 256>>>(parts, 3, TOT, bm1, (const float*)0, h1, TOT, CS, 1);
    gemm64<<<dim3(CS/64, LL/64, 3), 256>>>(h1, Wm2, parts, CS, CS, CS, CS/3, CS, TOT);
    combine<<<(TOT+255)/256, 256>>>(parts, 3, TOT, bm2, (const float*)0, h2, TOT, CS, 1);
    gemm64<<<dim3(CS/64, LL/64, 3), 256>>>(h2, Wm3, parts, CS, CS, CS, CS/3, CS, TOT);
    combine<<<(TOT+255)/256, 256>>>(parts, 3, TOT, bm3, s1, pre, TOT, CS, 0);
    lnorm<<<LL, 128>>>(pre, g2, b2, out);
}

// round 3
// speedup vs baseline: 1.3603x; 1.3603x over previous
#include <cuda_runtime.h>
#include <math.h>

#define LL 512
#define CS 384
#define CZ 256
#define PW 1152
#define SH 3648
#define WLL 0.57735026918962576f
#define WCC 0.23570226039551584f

__device__ float g_Wcat[CS * PW];
__device__ float g_proj[LL * PW];   // [q 0|k 192|v 384|qp 576|kp 720|vp 864]
__device__ float g_R[LL * 9];
__device__ float g_t[LL * 3];
__device__ float g_coef[12];
__device__ float g_qpp[LL * 144];       // row-major (per-i use)
__device__ float g_kT[192 * LL];        // j-contiguous
__device__ float g_vT[192 * LL];        // j-contiguous
__device__ float g_kppT[144 * LL];      // j-contiguous
__device__ float g_vppT[288 * LL];      // j-contiguous
__device__ float g_shid[LL * SH];
__device__ float g_parts[4 * LL * CS];
__device__ float g_s1[LL * CS];
__device__ float g_h1[LL * CS];
__device__ float g_h2[LL * CS];

__global__ void pack_prep(const float* __restrict__ Wq, const float* __restrict__ Wk,
                          const float* __restrict__ Wv, const float* __restrict__ Wqp,
                          const float* __restrict__ Wkp, const float* __restrict__ Wvp,
                          const float* __restrict__ quat, const float* __restrict__ trsl,
                          const float* __restrict__ scale)
{
    int idx = blockIdx.x * blockDim.x + threadIdx.x;
    if (idx < CS * PW) {
        int r = idx / PW, c = idx - r * PW;
        float v;
        if      (c < 192)  v = Wq [r*192 + c];
        else if (c < 384)  v = Wk [r*192 + c-192];
        else if (c < 576)  v = Wv [r*192 + c-384];
        else if (c < 720)  v = Wqp[r*144 + c-576];
        else if (c < 864)  v = Wkp[r*144 + c-720];
        else               v = Wvp[r*288 + c-864];
        g_Wcat[idx] = v;
    }
    if (idx < LL) {
        float w = quat[idx*4], x = quat[idx*4+1], y = quat[idx*4+2], z = quat[idx*4+3];
        float inv = rsqrtf(w*w + x*x + y*y + z*z);
        w *= inv; x *= inv; y *= inv; z *= inv;
        float* R = g_R + idx*9;
        R[0]=1.f-2.f*(y*y+z*z); R[1]=2.f*(x*y-w*z);     R[2]=2.f*(x*z+w*y);
        R[3]=2.f*(x*y+w*z);     R[4]=1.f-2.f*(x*x+z*z); R[5]=2.f*(y*z-w*x);
        R[6]=2.f*(x*z-w*y);     R[7]=2.f*(y*z+w*x);     R[8]=1.f-2.f*(x*x+y*y);
        g_t[idx*3]=trsl[idx*3]; g_t[idx*3+1]=trsl[idx*3+1]; g_t[idx*3+2]=trsl[idx*3+2];
    }
    if (idx < 12) g_coef[idx] = 0.5f * WCC * log1pf(expf(scale[idx]));
}

// per-i: transform points (write transposed kpp/vpp), transpose k/v
__global__ void transform()
{
    int i = blockIdx.x, pt = threadIdx.x;   // 384 threads
    // k/v transpose into j-contiguous layout
    if (pt < 192) g_kT[pt * LL + i] = g_proj[(size_t)i*PW + 192 + pt];
    else          g_vT[(pt-192) * LL + i] = g_proj[(size_t)i*PW + 384 + (pt-192)];
    if (pt >= 192) return;
    const float* R = g_R + i*9;
    const float* t = g_t + i*3;
    const float* src;
    if (pt < 48)      src = g_proj + (size_t)i*PW + 576 + pt*3;
    else if (pt < 96) src = g_proj + (size_t)i*PW + 720 + (pt-48)*3;
    else              src = g_proj + (size_t)i*PW + 864 + (pt-96)*3;
    float px = src[0], py = src[1], pz = src[2];
    float ox = R[0]*px + R[1]*py + R[2]*pz + t[0];
    float oy = R[3]*px + R[4]*py + R[5]*pz + t[1];
    float oz = R[6]*px + R[7]*py + R[8]*pz + t[2];
    if (pt < 48) {
        float* d = g_qpp + i*144 + pt*3;
        d[0] = ox; d[1] = oy; d[2] = oz;
    } else if (pt < 96) {
        int p = pt - 48;
        g_kppT[(p*3+0)*LL + i] = ox;
        g_kppT[(p*3+1)*LL + i] = oy;
        g_kppT[(p*3+2)*LL + i] = oz;
    } else {
        int p = pt - 96;
        g_vppT[(p*3+0)*LL + i] = ox;
        g_vppT[(p*3+1)*LL + i] = oy;
        g_vppT[(p*3+2)*LL + i] = oz;
    }
}

// 64x64 tile SGEMM, 256 threads, 4x4 per thread, split-K along gridDim.z
__global__ __launch_bounds__(256) void gemm64(const float* __restrict__ A,
                                              const float* __restrict__ B,
                                              float* __restrict__ C,
                                              int lda, int ldb, int ldc,
                                              int kSlice, int K, int partStride)
{
    __shared__ float As[16][64];
    __shared__ float Bs[16][64];
    int n0 = blockIdx.x * 64, m0 = blockIdx.y * 64;
    int k0 = blockIdx.z * kSlice;
    int kend = min(K, k0 + kSlice);
    float* Cc = C + (size_t)blockIdx.z * partStride;
    int tid = threadIdx.x;
    int tx = tid & 15, ty = tid >> 4;
    int ar = tid >> 2, ac = (tid & 3) << 2;
    float acc[4][4] = {};
    for (int kt = k0; kt < kend; kt += 16) {
        float4 av = *(const float4*)(A + (size_t)(m0 + ar) * lda + kt + ac);
        As[ac+0][ar] = av.x; As[ac+1][ar] = av.y; As[ac+2][ar] = av.z; As[ac+3][ar] = av.w;
        *(float4*)&Bs[ty][tx << 2] = *(const float4*)(B + (size_t)(kt + ty) * ldb + n0 + (tx << 2));
        __syncthreads();
        #pragma unroll
        for (int kk = 0; kk < 16; kk++) {
            float4 a = *(float4*)&As[kk][ty << 2];
            float4 b = *(float4*)&Bs[kk][tx << 2];
            acc[0][0]=fmaf(a.x,b.x,acc[0][0]); acc[0][1]=fmaf(a.x,b.y,acc[0][1]);
            acc[0][2]=fmaf(a.x,b.z,acc[0][2]); acc[0][3]=fmaf(a.x,b.w,acc[0][3]);
            acc[1][0]=fmaf(a.y,b.x,acc[1][0]); acc[1][1]=fmaf(a.y,b.y,acc[1][1]);
            acc[1][2]=fmaf(a.y,b.z,acc[1][2]); acc[1][3]=fmaf(a.y,b.w,acc[1][3]);
            acc[2][0]=fmaf(a.z,b.x,acc[2][0]); acc[2][1]=fmaf(a.z,b.y,acc[2][1]);
            acc[2][2]=fmaf(a.z,b.z,acc[2][2]); acc[2][3]=fmaf(a.z,b.w,acc[2][3]);
            acc[3][0]=fmaf(a.w,b.x,acc[3][0]); acc[3][1]=fmaf(a.w,b.y,acc[3][1]);
            acc[3][2]=fmaf(a.w,b.z,acc[3][2]); acc[3][3]=fmaf(a.w,b.w,acc[3][3]);
        }
        __syncthreads();
    }
    #pragma unroll
    for (int r = 0; r < 4; r++)
        *(float4*)(Cc + (size_t)(m0 + (ty<<2) + r) * ldc + n0 + (tx<<2)) =
            make_float4(acc[r][0], acc[r][1], acc[r][2], acc[r][3]);
}

__global__ void combine(const float* __restrict__ parts, int nparts, int partStride,
                        const float* __restrict__ bias, float* __restrict__ out,
                        int total, int N)
{
    int idx = blockIdx.x * blockDim.x + threadIdx.x;
    if (idx >= total) return;
    float v = parts[idx];
    for (int p = 1; p < nparts; p++) v += parts[(size_t)p * partStride + idx];
    v += bias[idx % N];
    out[idx] = fmaxf(v, 0.f);
}

// split-K combine + bias + residual + layernorm fused
__global__ void ln_combine(const float* __restrict__ parts, int nparts, int partStride,
                           const float* __restrict__ bias, const float* __restrict__ resid,
                           const float* __restrict__ gg, const float* __restrict__ bb,
                           float* __restrict__ out)
{
    int i = blockIdx.x, t = threadIdx.x;   // 128 threads
    float v[3];
    #pragma unroll
    for (int k = 0; k < 3; k++) {
        int c = t + k * 128;
        size_t off = (size_t)i * CS + c;
        float x = parts[off];
        for (int p = 1; p < nparts; p++) x += parts[(size_t)p * partStride + off];
        v[k] = x + bias[c] + resid[off];
    }
    float s = v[0]+v[1]+v[2], q = v[0]*v[0]+v[1]*v[1]+v[2]*v[2];
    #pragma unroll
    for (int o = 16; o; o >>= 1) {
        s += __shfl_xor_sync(0xffffffffu, s, o);
        q += __shfl_xor_sync(0xffffffffu, q, o);
    }
    __shared__ float ss[4], sq[4];
    int w = t >> 5, lane = t & 31;
    if (lane == 0) { ss[w] = s; sq[w] = q; }
    __syncthreads();
    if (t == 0) {
        float S = ss[0]+ss[1]+ss[2]+ss[3], Q = sq[0]+sq[1]+sq[2]+sq[3];
        float m = S * (1.f/CS);
        ss[0] = m; sq[0] = rsqrtf(Q*(1.f/CS) - m*m + 1e-5f);
    }
    __syncthreads();
    float m = ss[0], r = sq[0];
    float* o = out + (size_t)i * CS;
    #pragma unroll
    for (int k = 0; k < 3; k++) {
        int c = t + k * 128;
        o[c] = (v[k]-m)*r*gg[c] + bb[c];
    }
}

// fused attention: one CTA per query row i
__global__ __launch_bounds__(256) void attn(const float* __restrict__ z,
                                            const float* __restrict__ Wb)
{
    __shared__ float sA[LL * 12];     // 24 KB logits/weights
    __shared__ float sWb[CZ * 12];    // 12 KB
    __shared__ float sq[192], sqpp[144], sR[9], st3[3], scoef[12], sOVP[288];

    int i = blockIdx.x, tid = threadIdx.x;
    int lane = tid & 31, w = tid >> 5;
    const float* zrow = z + (size_t)i * LL * CZ;

    for (int x = tid; x < CZ*12; x += 256) sWb[x] = Wb[x];
    if (tid < 192) sq[tid] = g_proj[(size_t)i * PW + tid];
    if (tid < 144) sqpp[tid] = g_qpp[i*144 + tid];
    if (tid < 9)   sR[tid] = g_R[i*9 + tid];
    if (tid < 3)   st3[tid] = g_t[i*3 + tid];
    if (tid < 12)  scoef[tid] = g_coef[tid];
    __syncthreads();

    // ---- phase 1: logits for rows j=tid and j=tid+256 ----
    {
        const float* zr0 = zrow + (size_t)tid * CZ;
        const float* zr1 = zr0 + 256 * CZ;
        float acc0[12] = {}, acc1[12] = {};
        for (int c = 0; c < CZ; c += 8) {
            float zz0[8], zz1[8];
            *(float4*)&zz0[0] = *(const float4*)(zr0 + c);
            *(float4*)&zz0[4] = *(const float4*)(zr0 + c + 4);
            *(float4*)&zz1[0] = *(const float4*)(zr1 + c);
            *(float4*)&zz1[4] = *(const float4*)(zr1 + c + 4);
            #pragma unroll
            for (int cc = 0; cc < 8; cc++) {
                const float4* wp = (const float4*)(sWb + (c+cc)*12);
                float4 w0 = wp[0], w1 = wp[1], w2 = wp[2];
                float f0 = zz0[cc], f1 = zz1[cc];
                acc0[0]=fmaf(f0,w0.x,acc0[0]); acc0[1]=fmaf(f0,w0.y,acc0[1]);
                acc0[2]=fmaf(f0,w0.z,acc0[2]); acc0[3]=fmaf(f0,w0.w,acc0[3]);
                acc0[4]=fmaf(f0,w1.x,acc0[4]); acc0[5]=fmaf(f0,w1.y,acc0[5]);
                acc0[6]=fmaf(f0,w1.z,acc0[6]); acc0[7]=fmaf(f0,w1.w,acc0[7]);
                acc0[8]=fmaf(f0,w2.x,acc0[8]); acc0[9]=fmaf(f0,w2.y,acc0[9]);
                acc0[10]=fmaf(f0,w2.z,acc0[10]); acc0[11]=fmaf(f0,w2.w,acc0[11]);
                acc1[0]=fmaf(f1,w0.x,acc1[0]); acc1[1]=fmaf(f1,w0.y,acc1[1]);
                acc1[2]=fmaf(f1,w0.z,acc1[2]); acc1[3]=fmaf(f1,w0.w,acc1[3]);
                acc1[4]=fmaf(f1,w1.x,acc1[4]); acc1[5]=fmaf(f1,w1.y,acc1[5]);
                acc1[6]=fmaf(f1,w1.z,acc1[6]); acc1[7]=fmaf(f1,w1.w,acc1[7]);
                acc1[8]=fmaf(f1,w2.x,acc1[8]); acc1[9]=fmaf(f1,w2.y,acc1[9]);
                acc1[10]=fmaf(f1,w2.z,acc1[10]); acc1[11]=fmaf(f1,w2.w,acc1[11]);
            }
        }
        #pragma unroll
        for (int jj = 0; jj < 2; jj++) {
            int j = tid + jj * 256;
            const float* acc = jj ? acc1 : acc0;
            #pragma unroll
            for (int h = 0; h < 12; h++) {
                float qk = 0.f;
                #pragma unroll
                for (int d = 0; d < 16; d++)
                    qk = fmaf(sq[h*16+d], g_kT[(h*16+d)*LL + j], qk);
                float d2 = 0.f;
                #pragma unroll
                for (int e = 0; e < 12; e++) {
                    float dd = sqpp[h*12+e] - g_kppT[(h*12+e)*LL + j];
                    d2 = fmaf(dd, dd, d2);
                }
                sA[j*12 + h] = WLL * (qk * 0.25f + acc[h] - scoef[h] * d2);
            }
        }
    }
    __syncthreads();

    // ---- softmax over j for each head ----
    for (int h = w; h < 12; h += 8) {
        float m = -1e30f;
        for (int j = lane; j < LL; j += 32) m = fmaxf(m, sA[j*12+h]);
        #pragma unroll
        for (int o = 16; o; o >>= 1) m = fmaxf(m, __shfl_xor_sync(0xffffffffu, m, o));
        float sum = 0.f;
        for (int j = lane; j < LL; j += 32) {
            float e = __expf(sA[j*12+h] - m);
            sA[j*12+h] = e; sum += e;
        }
        #pragma unroll
        for (int o = 16; o; o >>= 1) sum += __shfl_xor_sync(0xffffffffu, sum, o);
        float inv = 1.f / sum;
        for (int j = lane; j < LL; j += 32) sA[j*12+h] *= inv;
    }
    __syncthreads();

    // ---- op = a^T @ z : 4 head-triples x 64 col-quads ----
    {
        int h0 = (tid >> 6) * 3;
        int cc = (tid & 63) << 2;
        float acc[3][4] = {};
        #pragma unroll 4
        for (int j = 0; j < LL; j++) {
            float4 zv = *(const float4*)(zrow + (size_t)j * CZ + cc);
            float a0 = sA[j*12+h0], a1 = sA[j*12+h0+1], a2 = sA[j*12+h0+2];
            acc[0][0]=fmaf(a0,zv.x,acc[0][0]); acc[0][1]=fmaf(a0,zv.y,acc[0][1]);
            acc[0][2]=fmaf(a0,zv.z,acc[0][2]); acc[0][3]=fmaf(a0,zv.w,acc[0][3]);
            acc[1][0]=fmaf(a1,zv.x,acc[1][0]); acc[1][1]=fmaf(a1,zv.y,acc[1][1]);
            acc[1][2]=fmaf(a1,zv.z,acc[1][2]); acc[1][3]=fmaf(a1,zv.w,acc[1][3]);
            acc[2][0]=fmaf(a2,zv.x,acc[2][0]); acc[2][1]=fmaf(a2,zv.y,acc[2][1]);
            acc[2][2]=fmaf(a2,zv.z,acc[2][2]); acc[2][3]=fmaf(a2,zv.w,acc[2][3]);
        }
        float* orow = g_shid + (size_t)i * SH;
        #pragma unroll
        for (int hh = 0; hh < 3; hh++)
            *(float4*)(orow + (h0+hh)*304 + cc) =
                make_float4(acc[hh][0], acc[hh][1], acc[hh][2], acc[hh][3]);
    }

    // ---- ov (16 dims) + ovp_g (24 dims) per head: j-contiguous streams ----
    if (tid < 240) {
        int h = tid / 20, o = (tid % 20) * 2;
        const float* s0;
        if (o < 16) s0 = g_vT + (h*16+o)*LL;
        else        s0 = g_vppT + (h*24+o-16)*LL;
        const float* s1p = s0 + LL;
        float a0 = 0.f, a1 = 0.f;
        #pragma unroll 4
        for (int j = 0; j < LL; j += 4) {
            float4 v0 = *(const float4*)(s0 + j);
            float4 v1 = *(const float4*)(s1p + j);
            float w0 = sA[(j+0)*12+h], w1 = sA[(j+1)*12+h];
            float w2 = sA[(j+2)*12+h], w3 = sA[(j+3)*12+h];
            a0 = fmaf(w0,v0.x,fmaf(w1,v0.y,fmaf(w2,v0.z,fmaf(w3,v0.w,a0))));
            a1 = fmaf(w0,v1.x,fmaf(w1,v1.y,fmaf(w2,v1.z,fmaf(w3,v1.w,a1))));
        }
        float* orow = g_shid + (size_t)i * SH + h * 304;
        if (o < 16) { orow[256+o] = a0; orow[257+o] = a1; }
        else        { sOVP[h*24 + o-16] = a0; sOVP[h*24 + o-15] = a1; }
    }
    __syncthreads();

    // ---- ovp = R^T (ovp_g - t), plus norms ----
    if (tid < 96) {
        int h = tid >> 3, vv = tid & 7;
        float gx = sOVP[h*24 + vv*3 + 0] - st3[0];
        float gy = sOVP[h*24 + vv*3 + 1] - st3[1];
        float gz = sOVP[h*24 + vv*3 + 2] - st3[2];
        float lx = sR[0]*gx + sR[3]*gy + sR[6]*gz;
        float ly = sR[1]*gx + sR[4]*gy + sR[7]*gz;
        float lz = sR[2]*gx + sR[5]*gy + sR[8]*gz;
        float* orow = g_shid + (size_t)i * SH + h * 304;
        orow[272 + vv*3 + 0] = lx;
        orow[272 + vv*3 + 1] = ly;
        orow[272 + vv*3 + 2] = lz;
        orow[296 + vv] = sqrtf(lx*lx + ly*ly + lz*lz);
    }
}

extern "C" void kernel_launch(void* const* d_in, const int* in_sizes, int n_in,
                              void* d_out, int out_size)
{
    const float* s    = (const float*)d_in[0];
    const float* z    = (const float*)d_in[1];
    const float* quat = (const float*)d_in[2];
    const float* trsl = (const float*)d_in[3];
    const float* Wq   = (const float*)d_in[4];
    const float* Wk   = (const float*)d_in[5];
    const float* Wv   = (const float*)d_in[6];
    const float* Wqp  = (const float*)d_in[7];
    const float* Wkp  = (const float*)d_in[8];
    const float* Wvp  = (const float*)d_in[9];
    const float* Wb   = (const float*)d_in[10];
    const float* Ws   = (const float*)d_in[11];
    const float* bs   = (const float*)d_in[12];
    const float* scale= (const float*)d_in[13];
    const float* g1   = (const float*)d_in[14];
    const float* b1   = (const float*)d_in[15];
    const float* Wm1  = (const float*)d_in[16];
    const float* bm1  = (const float*)d_in[17];
    const float* Wm2  = (const float*)d_in[18];
    const float* bm2  = (const float*)d_in[19];
    const float* Wm3  = (const float*)d_in[20];
    const float* bm3  = (const float*)d_in[21];
    const float* g2   = (const float*)d_in[22];
    const float* b2   = (const float*)d_in[23];
    float* out = (float*)d_out;

    void *pWcat, *pProj, *pShid, *pParts, *pS1, *pH1, *pH2;
    cudaGetSymbolAddress(&pWcat,  g_Wcat);
    cudaGetSymbolAddress(&pProj,  g_proj);
    cudaGetSymbolAddress(&pShid,  g_shid);
    cudaGetSymbolAddress(&pParts, g_parts);
    cudaGetSymbolAddress(&pS1,    g_s1);
    cudaGetSymbolAddress(&pH1,    g_h1);
    cudaGetSymbolAddress(&pH2,    g_h2);
    float* Wcat = (float*)pWcat;  float* proj = (float*)pProj;
    float* shid = (float*)pShid;  float* parts = (float*)pParts;
    float* s1 = (float*)pS1;      float* h1 = (float*)pH1;
    float* h2 = (float*)pH2;

    const int TOT = LL * CS;

    pack_prep<<<(CS*PW + 255)/256, 256>>>(Wq, Wk, Wv, Wqp, Wkp, Wvp, quat, trsl, scale);
    gemm64<<<dim3(PW/64, LL/64, 1), 256>>>(s, Wcat, proj, CS, PW, PW, CS, CS, 0);
    transform<<<LL, 384>>>();
    attn<<<LL, 256>>>(z, Wb);
    gemm64<<<dim3(CS/64, LL/64, 4), 256>>>(shid, Ws, parts, SH, CS, CS, SH/4, SH, TOT);
    ln_combine<<<LL, 128>>>(parts, 4, TOT, bs, s, g1, b1, s1);
    gemm64<<<dim3(CS/64, LL/64, 3), 256>>>(s1, Wm1, parts, CS, CS, CS, CS/3, CS, TOT);
    combine<<<(TOT+255)/256, 256>>>(parts, 3, TOT, bm1, h1, TOT, CS);
    gemm64<<<dim3(CS/64, LL/64, 3), 256>>>(h1, Wm2, parts, CS, CS, CS, CS/3, CS, TOT);
    combine<<<(TOT+255)/256, 256>>>(parts, 3, TOT, bm2, h2, TOT, CS);
    gemm64<<<dim3(CS/64, LL/64, 3), 256>>>(h2, Wm3, parts, CS, CS, CS, CS/3, CS, TOT);
    ln_combine<<<LL, 128>>>(parts, 3, TOT, bm3, s1, g2, b2, out);
}